// round 11
// baseline (speedup 1.0000x reference)
#include <cuda_runtime.h>
#include <cuda_fp16.h>
#include <math.h>
#include <stdint.h>

// Problem dims
#define B_  256
#define T_  512
#define F_  256
#define H_  1024
#define C_  128

// Tiling: 256 CTAs = 4 mb (64 rows) x 64 hb (16 h-units -> 64 gate cols), 2 CTAs/SM
#define NCTA 256
#define NTH  256     // 8 warps: 2 m-warps x 4 n-warps, warp tile m32 x n16
#define MT   64
#define HB   16
#define KT   128     // f16 K tile (8 k-steps of 16)
#define NT1  10      // (F+H)/KT
#define NT2  16      // (2H)/KT
#define NSTG 4

// A smem: row = 128 halfs (256B) + 16B pad -> conflict-free ldmatrix
#define ASTRIDE_B 272
#define ABUF      (64 * ASTRIDE_B)      // 17408 B per stage
#define BIAS_OFF  (NSTG * ABUF)
#define SMEM_BYTES (BIAS_OFF + 128 * 4)

// Persistent scratch
__device__ __align__(16) __half g_h1[2][B_][H_];
__device__ __align__(16) __half g_h2[2][B_][H_];
__device__ __align__(16) __half g_yh[(long)B_ * T_ * F_];
// Packed f16 weights in mma B-fragment order: [hb][tile][wn][j][lane] uint4 (1024/tile)
__device__ __align__(16) uint4 g_Wp1h[64L * NT1 * 1024];
__device__ __align__(16) uint4 g_Wp2h[64L * NT2 * 1024];
__device__ unsigned g_cnt = 0;
__device__ volatile unsigned g_gen = 0;

__device__ __forceinline__ void grid_barrier() {
    __syncthreads();
    if (threadIdx.x == 0) {
        unsigned my = g_gen;
        __threadfence();
        if (atomicAdd(&g_cnt, 1u) == NCTA - 1) {
            g_cnt = 0;
            __threadfence();
            g_gen = my + 1;
        } else {
            while (g_gen == my) { }
            __threadfence();
        }
    }
    __syncthreads();
}

__device__ __forceinline__ void mma_f16(float* c, const uint32_t* a, uint32_t b0, uint32_t b1) {
    asm volatile(
        "mma.sync.aligned.m16n8k16.row.col.f32.f16.f16.f32 "
        "{%0,%1,%2,%3}, {%4,%5,%6,%7}, {%8,%9}, {%0,%1,%2,%3};"
        : "+f"(c[0]), "+f"(c[1]), "+f"(c[2]), "+f"(c[3])
        : "r"(a[0]), "r"(a[1]), "r"(a[2]), "r"(a[3]), "r"(b0), "r"(b1));
}

__device__ __forceinline__ void ldsm4(uint32_t* a, uint32_t addr) {
    asm volatile("ldmatrix.sync.aligned.m8n8.x4.shared.b16 {%0,%1,%2,%3}, [%4];"
        : "=r"(a[0]), "=r"(a[1]), "=r"(a[2]), "=r"(a[3]) : "r"(addr));
}

__device__ __forceinline__ void cp16(uint32_t dst, const void* src) {
    asm volatile("cp.async.cg.shared.global [%0], [%1], 16;" :: "r"(dst), "l"(src));
}
#define CP_COMMIT()  asm volatile("cp.async.commit_group;" ::: "memory")
#define CP_WAIT2()   asm volatile("cp.async.wait_group 2;" ::: "memory")
#define CP_WAIT0()   asm volatile("cp.async.wait_group 0;" ::: "memory")

__device__ __forceinline__ float fsig(float x) { return 1.f / (1.f + expf(-x)); }

// ---------------- prep: f16 convert y + pack weights into B-fragment order ----------
// m16n8k16 row.col B fragment. Per tile (KT=128 -> 8 k-steps), per n-warp wn:
// j = khalf*4 + ni*2 + kspair  (khalf = ks>>2, kspair = (ks>>1)&1)
// uint4 comps: {b0 ks even, b1 ks even, b0 ks odd, b1 ks odd}
__device__ void pack_weights(uint4* dst, const float* __restrict__ Wih,
                             const float* __restrict__ Whh, int wih_k, int NT,
                             long n_items, long tid, long nth)
{
    for (long i = tid; i < n_items; i += nth) {
        int lane = (int)(i & 31);
        int j    = (int)((i >> 5) & 7);
        int wn   = (int)((i >> 8) & 3);
        int tile = (int)((i >> 10) % NT);
        int hb   = (int)((i >> 10) / NT);
        int kc = lane & 3, nr = lane >> 2;
        int khalf = j >> 2, ni = (j >> 1) & 1, kp = j & 1;
        int ncol = wn * 16 + ni * 8 + nr;
        long grow = (long)((ncol >> 4) * H_ + hb * 16 + (ncol & 15));
        int kb = tile * KT + khalf * 64 + kp * 32 + 2 * kc;
        uint32_t comp[4];
        #pragma unroll
        for (int q = 0; q < 4; q++) {
            int k = kb + (q & 1) * 8 + (q >> 1) * 16;
            const float* s = (k < wih_k) ? (Wih + grow * wih_k + k)
                                         : (Whh + grow * H_ + (k - wih_k));
            __half2 h = __floats2half2_rn(s[0], s[1]);
            comp[q] = *(uint32_t*)&h;
        }
        dst[i] = make_uint4(comp[0], comp[1], comp[2], comp[3]);
    }
}

__global__ void prep_kernel(const float* __restrict__ y,
                            const float* __restrict__ Wih1, const float* __restrict__ Whh1,
                            const float* __restrict__ Wih2, const float* __restrict__ Whh2)
{
    long tid = (long)blockIdx.x * blockDim.x + threadIdx.x;
    long nth = (long)gridDim.x * blockDim.x;

    for (long i = tid; i < (long)B_ * T_ * F_ / 2; i += nth) {
        float2 v = ((const float2*)y)[i];
        __half2 h = __floats2half2_rn(v.x, v.y);
        ((__half2*)g_yh)[i] = h;
    }
    pack_weights(g_Wp1h, Wih1, Whh1, F_, NT1, 64L * NT1 * 1024, tid, nth);
    pack_weights(g_Wp2h, Wih2, Whh2, H_, NT2, 64L * NT2 * 1024, tid, nth);
}

// ---------------- main persistent kernel ----------------

struct LayerCtx {
    const __half* a0; long a0s; int ks0;   // tiles < ks0 from a0
    const __half* a1;                       // stride H_
    const uint4*  wp;                       // packed fragments, per-hb base
    int nt;
};

__device__ __forceinline__ void run_layer(
    char* smem, uint32_t smem_u32, const LayerCtx& L,
    const float* __restrict__ biasL, float* cst,
    __half* __restrict__ hout, int mb, int hb, bool extra_tanh)
{
    const int tid  = threadIdx.x;
    const int lane = tid & 31, wid = tid >> 5;
    const int wm = wid >> 2, wn = wid & 3;          // 2 m-warps x 4 n-warps (wn = gate)
    const int r4 = lane >> 2, kc = lane & 3;
    const int lr  = tid >> 2;                        // A loader row 0..63
    const int lq  = (tid & 3);                       // 64B quarter of the row

    __syncthreads();   // protect stage buffers vs previous epilogue readers

    float acc[2][2][4];
    #pragma unroll
    for (int i = 0; i < 2; i++)
        #pragma unroll
        for (int j = 0; j < 2; j++)
            #pragma unroll
            for (int q = 0; q < 4; q++) acc[i][j][q] = 0.f;

    auto issueA = [&](int kt) {
        uint32_t d = smem_u32 + (kt & (NSTG - 1)) * ABUF + lr * ASTRIDE_B + lq * 64;
        const __half* s = (kt < L.ks0) ? (L.a0 + (long)lr * L.a0s + kt * KT)
                                       : (L.a1 + (long)lr * H_ + (kt - L.ks0) * KT);
        s += lq * 32;
        cp16(d,      s);
        cp16(d + 16, s + 8);
        cp16(d + 32, s + 16);
        cp16(d + 48, s + 24);
        CP_COMMIT();
    };

    const uint4* wbase = L.wp + (long)wn * 256 + lane;

    // ldmatrix lane address (fixed per thread)
    const uint32_t arow = (uint32_t)((wm * 32 + (lane & 7) + ((lane >> 3) & 1) * 8) * ASTRIDE_B
                                     + (lane >> 4) * 16);

    // 4-stage pipeline, distance 3; wait_group 2 => stage kt landed, kt+1/kt+2 in flight.
    issueA(0); issueA(1); issueA(2);
    const int nt = L.nt;
    for (int kt = 0; kt < nt; kt++) {
        const uint4* p = wbase + (long)kt * 1024;
        uint4 bb[4];
        // lo-half B fragments (ks 0..3): LDG latency overlaps the stage wait
        #pragma unroll
        for (int x = 0; x < 4; x++) bb[x] = __ldg(p + 32 * x);
        CP_WAIT2();
        __syncthreads();
        if (kt + 3 < nt) issueA(kt + 3); else CP_COMMIT();
        uint32_t a0r = smem_u32 + (kt & (NSTG - 1)) * ABUF + arow;
        uint32_t a1r = a0r + 16 * ASTRIDE_B;
        #pragma unroll
        for (int ks = 0; ks < 4; ks++) {
            uint32_t a0[4], a1[4];
            ldsm4(a0, a0r + ks * 32);
            ldsm4(a1, a1r + ks * 32);
            #pragma unroll
            for (int ni = 0; ni < 2; ni++) {
                uint4 w = bb[ni * 2 + ((ks >> 1) & 1)];
                uint32_t b0 = (ks & 1) ? w.z : w.x;
                uint32_t b1 = (ks & 1) ? w.w : w.y;
                mma_f16(acc[0][ni], a0, b0, b1);
                mma_f16(acc[1][ni], a1, b0, b1);
            }
        }
        // hi-half B fragments (ks 4..7): LDG latency overlaps lo-half mma retirement
        #pragma unroll
        for (int x = 0; x < 4; x++) bb[x] = __ldg(p + 32 * (4 + x));
        #pragma unroll
        for (int ks = 0; ks < 4; ks++) {
            uint32_t a0[4], a1[4];
            ldsm4(a0, a0r + (ks + 4) * 32);
            ldsm4(a1, a1r + (ks + 4) * 32);
            #pragma unroll
            for (int ni = 0; ni < 2; ni++) {
                uint4 w = bb[ni * 2 + ((ks >> 1) & 1)];
                uint32_t b0 = (ks & 1) ? w.z : w.x;
                uint32_t b1 = (ks & 1) ? w.w : w.y;
                mma_f16(acc[0][ni], a0, b0, b1);
                mma_f16(acc[1][ni], a1, b0, b1);
            }
        }
    }
    CP_WAIT0();
    __syncthreads();   // before reusing smem as gates

    // Epilogue: gates -> smem f32 [4 gate][64 row][17], then cell update
    float* gates = (float*)smem;
    #pragma unroll
    for (int mi = 0; mi < 2; mi++)
        #pragma unroll
        for (int ni = 0; ni < 2; ni++) {
            int row = wm * 32 + mi * 16 + r4;
            int u = ni * 8 + kc * 2;          // unit within gate (gate == wn)
            float* gb = gates + wn * (64 * 17) + row * 17 + u;
            gb[0]          = acc[mi][ni][0];
            gb[1]          = acc[mi][ni][1];
            gb[8 * 17]     = acc[mi][ni][2];
            gb[8 * 17 + 1] = acc[mi][ni][3];
        }
    __syncthreads();

    #pragma unroll
    for (int j = 0; j < 4; j++) {
        int idx = j * NTH + tid;
        int row = idx >> 4, col = idx & 15;
        float gi = gates[0 * 1088 + row * 17 + col] + biasL[0 * 16 + col];
        float gf = gates[1 * 1088 + row * 17 + col] + biasL[1 * 16 + col];
        float gg = gates[2 * 1088 + row * 17 + col] + biasL[2 * 16 + col];
        float go = gates[3 * 1088 + row * 17 + col] + biasL[3 * 16 + col];
        float ii = fsig(gi), ff = fsig(gf);
        float g2 = tanhf(gg), oo = fsig(go);
        float cn = ff * cst[j] + ii * g2;
        cst[j] = cn;
        float h = oo * tanhf(cn);
        if (extra_tanh) h = tanhf(h);
        __half hh = __float2half_rn(h);
        __stcg((unsigned short*)&hout[(long)(mb * MT + row) * H_ + hb * HB + col],
               __half_as_ushort(hh));
    }
}

__global__ void __launch_bounds__(NTH, 2) lstm_fused(
    const float* __restrict__ bih1, const float* __restrict__ bhh1,
    const float* __restrict__ bih2, const float* __restrict__ bhh2,
    const float* __restrict__ Wout, const float* __restrict__ bout,
    float* __restrict__ out)
{
    extern __shared__ char smem[];
    uint32_t smem_u32;
    asm("{ .reg .u64 t; cvta.to.shared.u64 t, %1; cvt.u32.u64 %0, t; }"
        : "=r"(smem_u32) : "l"(smem));
    const int tid = threadIdx.x;
    const int mb = (int)(blockIdx.x >> 6);   // 0..3
    const int hb = (int)(blockIdx.x & 63);   // 0..63
    float* bias_s = (float*)(smem + BIAS_OFF);

    for (int i = tid; i < MT * HB; i += NTH) {
        int r = i >> 4, c = i & 15;
        g_h1[0][mb * MT + r][hb * HB + c] = __float2half(0.f);
        g_h2[0][mb * MT + r][hb * HB + c] = __float2half(0.f);
    }
    if (tid < 128) {
        int l = tid >> 6, g = (tid >> 4) & 3, u = tid & 15;
        int grow = g * H_ + hb * HB + u;
        bias_s[tid] = (l == 0) ? (bih1[grow] + bhh1[grow]) : (bih2[grow] + bhh2[grow]);
    }
    float c1[4], c2[4];
    #pragma unroll
    for (int j = 0; j < 4; j++) { c1[j] = 0.f; c2[j] = 0.f; }
    __syncthreads();
    grid_barrier();

    const uint4* wp1 = g_Wp1h + (long)hb * NT1 * 1024;
    const uint4* wp2 = g_Wp2h + (long)hb * NT2 * 1024;

    for (int t = 0; t < T_; t++) {
        int rb = t & 1, wb = rb ^ 1;
        {
            LayerCtx L;
            L.a0 = g_yh + (long)(mb * MT) * (T_ * F_) + (long)t * F_;
            L.a0s = (long)(T_ * F_);
            L.ks0 = F_ / KT;                 // 2
            L.a1 = &g_h1[rb][mb * MT][0];
            L.wp = wp1;
            L.nt = NT1;
            run_layer(smem, smem_u32, L, bias_s, c1, &g_h1[wb][0][0], mb, hb, false);
        }
        grid_barrier();
        {
            LayerCtx L;
            L.a0 = &g_h1[wb][mb * MT][0];
            L.a0s = (long)H_;
            L.ks0 = H_ / KT;                 // 8
            L.a1 = &g_h2[rb][mb * MT][0];
            L.wp = wp2;
            L.nt = NT2;
            run_layer(smem, smem_u32, L, bias_s + 64, c2, &g_h2[wb][0][0], mb, hb, true);
        }
        // single barrier per step: remaining hazards ordered by step t+1's barrier (R5)
    }
    grid_barrier();

    // Output projection: h2 final in buffer 0 (T even). First 128 CTAs, 1 elem/thread.
    {
        int gid = (int)blockIdx.x * NTH + tid;
        if (gid < B_ * C_) {
            int b = gid >> 7, cc = gid & 127;
            float acc = __ldg(&bout[cc]);
            const __half* hr = &g_h2[0][b][0];
            const float*  wr = &Wout[(long)cc * H_];
            #pragma unroll 4
            for (int k = 0; k < H_ / 8; k++) {
                uint4 hk = __ldcg((const uint4*)(hr + k * 8));
                const __half2* hp = (const __half2*)&hk;
                float4 w0 = __ldg((const float4*)(wr + k * 8));
                float4 w1 = __ldg((const float4*)(wr + k * 8 + 4));
                float2 p0 = __half22float2(hp[0]);
                float2 p1 = __half22float2(hp[1]);
                float2 p2 = __half22float2(hp[2]);
                float2 p3 = __half22float2(hp[3]);
                acc += p0.x * w0.x + p0.y * w0.y + p1.x * w0.z + p1.y * w0.w;
                acc += p2.x * w1.x + p2.y * w1.y + p3.x * w1.z + p3.y * w1.w;
            }
            out[gid] = fmaxf(acc, 0.f);
        }
    }
}

extern "C" void kernel_launch(void* const* d_in, const int* in_sizes, int n_in,
                              void* d_out, int out_size) {
    const float* y    = (const float*)d_in[0];
    const float* Wih1 = (const float*)d_in[1];
    const float* Whh1 = (const float*)d_in[2];
    const float* bih1 = (const float*)d_in[3];
    const float* bhh1 = (const float*)d_in[4];
    const float* Wih2 = (const float*)d_in[5];
    const float* Whh2 = (const float*)d_in[6];
    const float* bih2 = (const float*)d_in[7];
    const float* bhh2 = (const float*)d_in[8];
    const float* Wout = (const float*)d_in[9];
    const float* bout = (const float*)d_in[10];
    float* out = (float*)d_out;

    static int smem_set = 0;
    if (!smem_set) {
        cudaFuncSetAttribute(lstm_fused, cudaFuncAttributeMaxDynamicSharedMemorySize, SMEM_BYTES);
        smem_set = 1;
    }

    prep_kernel<<<2048, 256>>>(y, Wih1, Whh1, Wih2, Whh2);
    lstm_fused<<<NCTA, NTH, SMEM_BYTES>>>(bih1, bhh1, bih2, bhh2, Wout, bout, out);
}

// round 13
// speedup vs baseline: 1.2962x; 1.2962x over previous
#include <cuda_runtime.h>
#include <cuda_fp16.h>
#include <math.h>
#include <stdint.h>

// Problem dims
#define B_  256
#define T_  512
#define F_  256
#define H_  1024
#define C_  128

// Tiling: 256 CTAs = 4 mb (64 rows) x 64 hb (16 h-units -> 64 gate cols), 2 CTAs/SM
#define NCTA 256
#define NTH  256     // 8 warps: 2 m-warps x 4 n-warps, warp tile m32 x n16
#define MT   64
#define HB   16
#define KT   64      // f16 K tile (4 k-steps of 16)
#define NT1  20      // (F+H)/KT
#define NT2  32      // (2H)/KT
#define NSTG 4

// A smem: row stride 144B (72 halfs) -> conflict-free ldmatrix
#define ASTRIDE_B 144
#define ABUF      (64 * ASTRIDE_B)      // 9216 B per stage
#define BIAS_OFF  (NSTG * ABUF)
#define SMEM_BYTES (BIAS_OFF + 128 * 4)

// Persistent scratch
__device__ __align__(16) __half g_h1[2][B_][H_];
__device__ __align__(16) __half g_h2[2][B_][H_];
__device__ __align__(16) __half g_yh[(long)B_ * T_ * F_];
// Packed f16 weights in mma B-fragment order: [hb][tile][wn][j][lane] uint4 (512/tile)
__device__ __align__(16) uint4 g_Wp1h[64L * NT1 * 512];
__device__ __align__(16) uint4 g_Wp2h[64L * NT2 * 512];
__device__ unsigned g_cnt = 0;
__device__ volatile unsigned g_gen = 0;

__device__ __forceinline__ void grid_barrier() {
    __syncthreads();
    if (threadIdx.x == 0) {
        unsigned my = g_gen;
        __threadfence();
        if (atomicAdd(&g_cnt, 1u) == NCTA - 1) {
            g_cnt = 0;
            __threadfence();
            g_gen = my + 1;
        } else {
            while (g_gen == my) { }
            __threadfence();
        }
    }
    __syncthreads();
}

__device__ __forceinline__ void mma_f16(float* c, const uint32_t* a, uint32_t b0, uint32_t b1) {
    asm volatile(
        "mma.sync.aligned.m16n8k16.row.col.f32.f16.f16.f32 "
        "{%0,%1,%2,%3}, {%4,%5,%6,%7}, {%8,%9}, {%0,%1,%2,%3};"
        : "+f"(c[0]), "+f"(c[1]), "+f"(c[2]), "+f"(c[3])
        : "r"(a[0]), "r"(a[1]), "r"(a[2]), "r"(a[3]), "r"(b0), "r"(b1));
}

__device__ __forceinline__ void ldsm4(uint32_t* a, uint32_t addr) {
    asm volatile("ldmatrix.sync.aligned.m8n8.x4.shared.b16 {%0,%1,%2,%3}, [%4];"
        : "=r"(a[0]), "=r"(a[1]), "=r"(a[2]), "=r"(a[3]) : "r"(addr));
}

__device__ __forceinline__ void cp16(uint32_t dst, const void* src) {
    asm volatile("cp.async.cg.shared.global [%0], [%1], 16;" :: "r"(dst), "l"(src));
}
#define CP_COMMIT()  asm volatile("cp.async.commit_group;" ::: "memory")
#define CP_WAIT2()   asm volatile("cp.async.wait_group 2;" ::: "memory")
#define CP_WAIT0()   asm volatile("cp.async.wait_group 0;" ::: "memory")

// Fast nonlinearities: MUFU-based, no slow paths. Clamp keeps __expf finite.
__device__ __forceinline__ float fsig(float x) {
    x = fminf(fmaxf(x, -30.f), 30.f);
    return __fdividef(1.f, 1.f + __expf(-x));
}
__device__ __forceinline__ float ftanh(float x) {
    x = fminf(fmaxf(x, -15.f), 15.f);
    float e = __expf(2.f * x);
    return __fdividef(e - 1.f, e + 1.f);
}

// ---------------- prep: f16 convert y + pack weights into B-fragment order ----------
// m16n8k16 row.col B fragment: lane needs b0 = W[n=nr][kb+2kc,+1], b1 = same k+8.
// CTA col c (0..63): gate = c>>4, unit = c&15. ncol = wn*16 + ni*8 + nr, ni in {0,1}.
// uint4 j = ni*2 + (ks>>1): {b0 ks even, b1 ks even, b0 ks odd, b1 ks odd}
__device__ void pack_weights(uint4* dst, const float* __restrict__ Wih,
                             const float* __restrict__ Whh, int wih_k, int NT,
                             long n_items, long tid, long nth)
{
    for (long i = tid; i < n_items; i += nth) {
        int lane = (int)(i & 31);
        int j    = (int)((i >> 5) & 3);
        int wn   = (int)((i >> 7) & 3);
        int tile = (int)((i >> 9) % NT);
        int hb   = (int)((i >> 9) / NT);
        int kc = lane & 3, nr = lane >> 2;
        int ni = j >> 1, ksa = 2 * (j & 1);
        int ncol = wn * 16 + ni * 8 + nr;
        long grow = (long)((ncol >> 4) * H_ + hb * 16 + (ncol & 15));
        int kb = tile * KT + ksa * 16 + 2 * kc;
        uint32_t comp[4];
        #pragma unroll
        for (int q = 0; q < 4; q++) {
            int k = kb + (q & 1) * 8 + (q >> 1) * 16;
            const float* s = (k < wih_k) ? (Wih + grow * wih_k + k)
                                         : (Whh + grow * H_ + (k - wih_k));
            __half2 h = __floats2half2_rn(s[0], s[1]);
            comp[q] = *(uint32_t*)&h;
        }
        dst[i] = make_uint4(comp[0], comp[1], comp[2], comp[3]);
    }
}

__global__ void prep_kernel(const float* __restrict__ y,
                            const float* __restrict__ Wih1, const float* __restrict__ Whh1,
                            const float* __restrict__ Wih2, const float* __restrict__ Whh2)
{
    long tid = (long)blockIdx.x * blockDim.x + threadIdx.x;
    long nth = (long)gridDim.x * blockDim.x;

    for (long i = tid; i < (long)B_ * T_ * F_ / 2; i += nth) {
        float2 v = ((const float2*)y)[i];
        __half2 h = __floats2half2_rn(v.x, v.y);
        ((__half2*)g_yh)[i] = h;
    }
    pack_weights(g_Wp1h, Wih1, Whh1, F_, NT1, 64L * NT1 * 512, tid, nth);
    pack_weights(g_Wp2h, Wih2, Whh2, H_, NT2, 64L * NT2 * 512, tid, nth);
}

// ---------------- main persistent kernel ----------------

struct LayerCtx {
    const __half* a0; long a0s; int ks0;   // tiles < ks0 from a0
    const __half* a1;                       // stride H_
    const uint4*  wp;                       // packed fragments, per-hb base
    int nt;
};

__device__ __forceinline__ void run_layer(
    char* smem, uint32_t smem_u32, const LayerCtx& L,
    const float* __restrict__ biasL, float* cst,
    __half* __restrict__ hout, int mb, int hb, bool extra_tanh)
{
    const int tid  = threadIdx.x;
    const int lane = tid & 31, wid = tid >> 5;
    const int wm = wid >> 2, wn = wid & 3;          // 2 m-warps x 4 n-warps (wn = gate)
    const int r4 = lane >> 2, kc = lane & 3;
    const int lr  = tid >> 2;                        // A loader row 0..63
    const int lc0 = (tid & 3) * 2;                   // 2 x 16B chunks per thread

    __syncthreads();   // protect stage buffers vs previous epilogue readers

    float acc[2][2][4];
    #pragma unroll
    for (int i = 0; i < 2; i++)
        #pragma unroll
        for (int j = 0; j < 2; j++)
            #pragma unroll
            for (int q = 0; q < 4; q++) acc[i][j][q] = 0.f;

    auto issueA = [&](int kt) {
        uint32_t d = smem_u32 + (kt & (NSTG - 1)) * ABUF + lr * ASTRIDE_B + lc0 * 16;
        const __half* s = (kt < L.ks0) ? (L.a0 + (long)lr * L.a0s + kt * KT)
                                       : (L.a1 + (long)lr * H_ + (kt - L.ks0) * KT);
        s += lc0 * 8;
        cp16(d, s);
        cp16(d + 16, s + 8);
        CP_COMMIT();
    };

    const uint4* wbase = L.wp + (long)wn * 128 + lane;
    auto loadB = [&](int kt, uint4* bb) {
        const uint4* p = wbase + (long)kt * 512;
        #pragma unroll
        for (int x = 0; x < 4; x++) bb[x] = __ldg(p + 32 * x);
    };

    // ldmatrix lane address (fixed per thread)
    const uint32_t arow = (uint32_t)((wm * 32 + (lane & 7) + ((lane >> 3) & 1) * 8) * ASTRIDE_B
                                     + (lane >> 4) * 16);

    auto mma_tile = [&](int kt, const uint4* bb) {
        uint32_t a0r = smem_u32 + (kt & (NSTG - 1)) * ABUF + arow;
        uint32_t a1r = a0r + 16 * ASTRIDE_B;
        #pragma unroll
        for (int ks = 0; ks < 4; ks++) {
            uint32_t a0[4], a1[4];
            ldsm4(a0, a0r + ks * 32);
            ldsm4(a1, a1r + ks * 32);
            #pragma unroll
            for (int ni = 0; ni < 2; ni++) {
                uint4 w = bb[ni * 2 + (ks >> 1)];
                uint32_t b0 = (ks & 1) ? w.z : w.x;
                uint32_t b1 = (ks & 1) ? w.w : w.y;
                mma_f16(acc[0][ni], a0, b0, b1);
                mma_f16(acc[1][ni], a1, b0, b1);
            }
        }
    };

    // 4-stage A pipeline (distance 3) + distance-1 register double-buffer for B.
    uint4 bbA[4], bbB[4];
    issueA(0); issueA(1); issueA(2);
    loadB(0, bbA);
    const int nt = L.nt;   // even (20 or 32)
    for (int kt = 0; kt < nt; kt += 2) {
        // even tile kt: consume bbA; prefetch B(kt+1) -> bbB (hidden under mma)
        CP_WAIT2();
        __syncthreads();
        loadB(kt + 1, bbB);
        if (kt + 3 < nt) issueA(kt + 3); else CP_COMMIT();
        mma_tile(kt, bbA);
        // odd tile kt+1: consume bbB; prefetch B(kt+2) -> bbA
        CP_WAIT2();
        __syncthreads();
        if (kt + 2 < nt) loadB(kt + 2, bbA);
        if (kt + 4 < nt) issueA(kt + 4); else CP_COMMIT();
        mma_tile(kt + 1, bbB);
    }
    CP_WAIT0();
    __syncthreads();   // before reusing smem as gates

    // Epilogue: gates -> smem f32 [4 gate][64 row][17], then cell update
    float* gates = (float*)smem;
    #pragma unroll
    for (int mi = 0; mi < 2; mi++)
        #pragma unroll
        for (int ni = 0; ni < 2; ni++) {
            int row = wm * 32 + mi * 16 + r4;
            int u = ni * 8 + kc * 2;          // unit within gate (gate == wn)
            float* gb = gates + wn * (64 * 17) + row * 17 + u;
            gb[0]          = acc[mi][ni][0];
            gb[1]          = acc[mi][ni][1];
            gb[8 * 17]     = acc[mi][ni][2];
            gb[8 * 17 + 1] = acc[mi][ni][3];
        }
    __syncthreads();

    #pragma unroll
    for (int j = 0; j < 4; j++) {
        int idx = j * NTH + tid;
        int row = idx >> 4, col = idx & 15;
        float gi = gates[0 * 1088 + row * 17 + col] + biasL[0 * 16 + col];
        float gf = gates[1 * 1088 + row * 17 + col] + biasL[1 * 16 + col];
        float gg = gates[2 * 1088 + row * 17 + col] + biasL[2 * 16 + col];
        float go = gates[3 * 1088 + row * 17 + col] + biasL[3 * 16 + col];
        float ii = fsig(gi), ff = fsig(gf);
        float g2 = ftanh(gg), oo = fsig(go);
        float cn = ff * cst[j] + ii * g2;
        cst[j] = cn;
        float h = oo * ftanh(cn);
        if (extra_tanh) h = ftanh(h);
        __half hh = __float2half_rn(h);
        __stcg((unsigned short*)&hout[(long)(mb * MT + row) * H_ + hb * HB + col],
               __half_as_ushort(hh));
    }
}

__global__ void __launch_bounds__(NTH, 2) lstm_fused(
    const float* __restrict__ bih1, const float* __restrict__ bhh1,
    const float* __restrict__ bih2, const float* __restrict__ bhh2,
    const float* __restrict__ Wout, const float* __restrict__ bout,
    float* __restrict__ out)
{
    extern __shared__ char smem[];
    uint32_t smem_u32;
    asm("{ .reg .u64 t; cvta.to.shared.u64 t, %1; cvt.u32.u64 %0, t; }"
        : "=r"(smem_u32) : "l"(smem));
    const int tid = threadIdx.x;
    const int mb = (int)(blockIdx.x >> 6);   // 0..3
    const int hb = (int)(blockIdx.x & 63);   // 0..63
    float* bias_s = (float*)(smem + BIAS_OFF);

    for (int i = tid; i < MT * HB; i += NTH) {
        int r = i >> 4, c = i & 15;
        g_h1[0][mb * MT + r][hb * HB + c] = __float2half(0.f);
        g_h2[0][mb * MT + r][hb * HB + c] = __float2half(0.f);
    }
    if (tid < 128) {
        int l = tid >> 6, g = (tid >> 4) & 3, u = tid & 15;
        int grow = g * H_ + hb * HB + u;
        bias_s[tid] = (l == 0) ? (bih1[grow] + bhh1[grow]) : (bih2[grow] + bhh2[grow]);
    }
    float c1[4], c2[4];
    #pragma unroll
    for (int j = 0; j < 4; j++) { c1[j] = 0.f; c2[j] = 0.f; }
    __syncthreads();
    grid_barrier();

    const uint4* wp1 = g_Wp1h + (long)hb * NT1 * 512;
    const uint4* wp2 = g_Wp2h + (long)hb * NT2 * 512;

    for (int t = 0; t < T_; t++) {
        int rb = t & 1, wb = rb ^ 1;
        {
            LayerCtx L;
            L.a0 = g_yh + (long)(mb * MT) * (T_ * F_) + (long)t * F_;
            L.a0s = (long)(T_ * F_);
            L.ks0 = F_ / KT;                 // 4
            L.a1 = &g_h1[rb][mb * MT][0];
            L.wp = wp1;
            L.nt = NT1;
            run_layer(smem, smem_u32, L, bias_s, c1, &g_h1[wb][0][0], mb, hb, false);
        }
        grid_barrier();
        {
            LayerCtx L;
            L.a0 = &g_h1[wb][mb * MT][0];
            L.a0s = (long)H_;
            L.ks0 = H_ / KT;                 // 16
            L.a1 = &g_h2[rb][mb * MT][0];
            L.wp = wp2;
            L.nt = NT2;
            run_layer(smem, smem_u32, L, bias_s + 64, c2, &g_h2[wb][0][0], mb, hb, true);
        }
        // single barrier per step: remaining hazards ordered by step t+1's barrier (R5)
    }
    grid_barrier();

    // Output projection: h2 final in buffer 0 (T even). First 128 CTAs, 1 elem/thread.
    {
        int gid = (int)blockIdx.x * NTH + tid;
        if (gid < B_ * C_) {
            int b = gid >> 7, cc = gid & 127;
            float acc = __ldg(&bout[cc]);
            const __half* hr = &g_h2[0][b][0];
            const float*  wr = &Wout[(long)cc * H_];
            #pragma unroll 4
            for (int k = 0; k < H_ / 8; k++) {
                uint4 hk = __ldcg((const uint4*)(hr + k * 8));
                const __half2* hp = (const __half2*)&hk;
                float4 w0 = __ldg((const float4*)(wr + k * 8));
                float4 w1 = __ldg((const float4*)(wr + k * 8 + 4));
                float2 p0 = __half22float2(hp[0]);
                float2 p1 = __half22float2(hp[1]);
                float2 p2 = __half22float2(hp[2]);
                float2 p3 = __half22float2(hp[3]);
                acc += p0.x * w0.x + p0.y * w0.y + p1.x * w0.z + p1.y * w0.w;
                acc += p2.x * w1.x + p2.y * w1.y + p3.x * w1.z + p3.y * w1.w;
            }
            out[gid] = fmaxf(acc, 0.f);
        }
    }
}

extern "C" void kernel_launch(void* const* d_in, const int* in_sizes, int n_in,
                              void* d_out, int out_size) {
    const float* y    = (const float*)d_in[0];
    const float* Wih1 = (const float*)d_in[1];
    const float* Whh1 = (const float*)d_in[2];
    const float* bih1 = (const float*)d_in[3];
    const float* bhh1 = (const float*)d_in[4];
    const float* Wih2 = (const float*)d_in[5];
    const float* Whh2 = (const float*)d_in[6];
    const float* bih2 = (const float*)d_in[7];
    const float* bhh2 = (const float*)d_in[8];
    const float* Wout = (const float*)d_in[9];
    const float* bout = (const float*)d_in[10];
    float* out = (float*)d_out;

    prep_kernel<<<2048, 256>>>(y, Wih1, Whh1, Wih2, Whh2);
    lstm_fused<<<NCTA, NTH, SMEM_BYTES>>>(bih1, bhh1, bih2, bhh2, Wout, bout, out);
}

// round 14
// speedup vs baseline: 1.3798x; 1.0645x over previous
#include <cuda_runtime.h>
#include <cuda_fp16.h>
#include <math.h>
#include <stdint.h>

// Problem dims
#define B_  256
#define T_  512
#define F_  256
#define H_  1024
#define C_  128

// Tiling: 256 CTAs = 4 mb (64 rows) x 64 hb (16 h-units -> 64 gate cols), 2 CTAs/SM
// 8 warps = 2 K-groups x (2 m-warps x 2 n-warps), warp tile m32 x n32
#define NCTA 256
#define NTH  256
#define MT   64
#define HB   16
#define KT   64      // f16 K tile (4 k-steps of 16); group g owns tiles kt&1==g
#define NT1  20      // (F+H)/KT
#define NT2  32      // (2H)/KT
#define NSTG 6       // A stage ring

// A smem: row stride 144B (72 halfs) -> conflict-free ldmatrix
#define ASTRIDE_B 144
#define ABUF      (64 * ASTRIDE_B)      // 9216 B per stage
#define BIAS_OFF  (NSTG * ABUF)         // 55296
#define SMEM_BYTES (BIAS_OFF + 128 * 4)

// Persistent scratch
__device__ __align__(16) __half g_h1[2][B_][H_];
__device__ __align__(16) __half g_h2[2][B_][H_];
__device__ __align__(16) __half g_yh[(long)B_ * T_ * F_];
// Packed f16 weights in B-fragment order: [hb][tile][wn(2)][j(8)][lane(32)] uint4 (512/tile)
__device__ __align__(16) uint4 g_Wp1h[64L * NT1 * 512];
__device__ __align__(16) uint4 g_Wp2h[64L * NT2 * 512];
__device__ unsigned g_cnt = 0;
__device__ volatile unsigned g_gen = 0;

__device__ __forceinline__ void grid_barrier() {
    __syncthreads();
    if (threadIdx.x == 0) {
        unsigned my = g_gen;
        __threadfence();
        if (atomicAdd(&g_cnt, 1u) == NCTA - 1) {
            g_cnt = 0;
            __threadfence();
            g_gen = my + 1;
        } else {
            while (g_gen == my) { }
            __threadfence();
        }
    }
    __syncthreads();
}

__device__ __forceinline__ void mma_f16(float* c, const uint32_t* a, uint32_t b0, uint32_t b1) {
    asm volatile(
        "mma.sync.aligned.m16n8k16.row.col.f32.f16.f16.f32 "
        "{%0,%1,%2,%3}, {%4,%5,%6,%7}, {%8,%9}, {%0,%1,%2,%3};"
        : "+f"(c[0]), "+f"(c[1]), "+f"(c[2]), "+f"(c[3])
        : "r"(a[0]), "r"(a[1]), "r"(a[2]), "r"(a[3]), "r"(b0), "r"(b1));
}

__device__ __forceinline__ void ldsm4(uint32_t* a, uint32_t addr) {
    asm volatile("ldmatrix.sync.aligned.m8n8.x4.shared.b16 {%0,%1,%2,%3}, [%4];"
        : "=r"(a[0]), "=r"(a[1]), "=r"(a[2]), "=r"(a[3]) : "r"(addr));
}

__device__ __forceinline__ void cp16(uint32_t dst, const void* src) {
    asm volatile("cp.async.cg.shared.global [%0], [%1], 16;" :: "r"(dst), "l"(src));
}
#define CP_COMMIT()  asm volatile("cp.async.commit_group;" ::: "memory")
#define CP_WAIT2()   asm volatile("cp.async.wait_group 2;" ::: "memory")
#define CP_WAIT0()   asm volatile("cp.async.wait_group 0;" ::: "memory")

// Fast nonlinearities: MUFU-based, no slow paths.
__device__ __forceinline__ float fsig(float x) {
    x = fminf(fmaxf(x, -30.f), 30.f);
    return __fdividef(1.f, 1.f + __expf(-x));
}
__device__ __forceinline__ float ftanh(float x) {
    x = fminf(fmaxf(x, -15.f), 15.f);
    float e = __expf(2.f * x);
    return __fdividef(e - 1.f, e + 1.f);
}

// ---------------- prep: f16 convert y + pack weights into B-fragment order ----------
// Warp (wm, wn) covers n cols wn*32 + ni*8 + nr, ni 0..3.
// j = ni*2 + kspair; uint4 comps {b0 ks=2kp, b1 ks=2kp, b0 ks=2kp+1, b1 ks=2kp+1}
__device__ void pack_weights(uint4* dst, const float* __restrict__ Wih,
                             const float* __restrict__ Whh, int wih_k, int NT,
                             long n_items, long tid, long nth)
{
    for (long i = tid; i < n_items; i += nth) {
        int lane = (int)(i & 31);
        int j    = (int)((i >> 5) & 7);
        int wn   = (int)((i >> 8) & 1);
        int tile = (int)((i >> 9) % NT);
        int hb   = (int)((i >> 9) / NT);
        int kc = lane & 3, nr = lane >> 2;
        int ni = j >> 1, ksa = 2 * (j & 1);
        int ncol = wn * 32 + ni * 8 + nr;
        long grow = (long)((ncol >> 4) * H_ + hb * 16 + (ncol & 15));
        int kb = tile * KT + ksa * 16 + 2 * kc;
        uint32_t comp[4];
        #pragma unroll
        for (int q = 0; q < 4; q++) {
            int k = kb + (q & 1) * 8 + (q >> 1) * 16;
            const float* s = (k < wih_k) ? (Wih + grow * wih_k + k)
                                         : (Whh + grow * H_ + (k - wih_k));
            __half2 h = __floats2half2_rn(s[0], s[1]);
            comp[q] = *(uint32_t*)&h;
        }
        dst[i] = make_uint4(comp[0], comp[1], comp[2], comp[3]);
    }
}

__global__ void prep_kernel(const float* __restrict__ y,
                            const float* __restrict__ Wih1, const float* __restrict__ Whh1,
                            const float* __restrict__ Wih2, const float* __restrict__ Whh2)
{
    long tid = (long)blockIdx.x * blockDim.x + threadIdx.x;
    long nth = (long)gridDim.x * blockDim.x;

    for (long i = tid; i < (long)B_ * T_ * F_ / 2; i += nth) {
        float2 v = ((const float2*)y)[i];
        __half2 h = __floats2half2_rn(v.x, v.y);
        ((__half2*)g_yh)[i] = h;
    }
    pack_weights(g_Wp1h, Wih1, Whh1, F_, NT1, 64L * NT1 * 512, tid, nth);
    pack_weights(g_Wp2h, Wih2, Whh2, H_, NT2, 64L * NT2 * 512, tid, nth);
}

// ---------------- main persistent kernel ----------------

struct LayerCtx {
    const __half* a0; long a0s; int ks0;   // tiles < ks0 from a0
    const __half* a1;                       // stride H_
    const uint4*  wp;                       // packed fragments, per-hb base
    int nt;                                 // multiple of 4
};

__device__ __forceinline__ void run_layer(
    char* smem, uint32_t smem_u32, const LayerCtx& L,
    const float* __restrict__ biasL, float* cst,
    __half* __restrict__ hout, int mb, int hb, bool extra_tanh)
{
    const int tid  = threadIdx.x;
    const int lane = tid & 31, wid = tid >> 5;
    const int g  = wid >> 2;                 // K-group: tiles kt&1 == g
    const int wm = (wid >> 1) & 1, wn = wid & 1;
    const int r4 = lane >> 2, kc = lane & 3;
    const int lr  = tid >> 2;                // A loader row 0..63
    const int lc0 = (tid & 3) * 2;           // 2 x 16B chunks per thread

    __syncthreads();   // protect stage ring vs previous epilogue readers

    float acc[2][4][4];
    #pragma unroll
    for (int i = 0; i < 2; i++)
        #pragma unroll
        for (int j = 0; j < 4; j++)
            #pragma unroll
            for (int q = 0; q < 4; q++) acc[i][j][q] = 0.f;

    const int nt = L.nt;
    auto issueA = [&](int kt) {
        uint32_t d = smem_u32 + (kt % NSTG) * ABUF + lr * ASTRIDE_B + lc0 * 16;
        const __half* s = (kt < L.ks0) ? (L.a0 + (long)lr * L.a0s + kt * KT)
                                       : (L.a1 + (long)lr * H_ + (kt - L.ks0) * KT);
        s += lc0 * 8;
        cp16(d, s);
        cp16(d + 16, s + 8);
        CP_COMMIT();
    };
    auto issue2 = [&](int k0, int k1) {
        if (k0 < nt) issueA(k0); else CP_COMMIT();
        if (k1 < nt) issueA(k1); else CP_COMMIT();
    };

    const uint4* wbase = L.wp + (long)wn * 256 + lane;
    auto loadBh = [&](int kt, int half, uint4* bb) {
        const uint4* p = wbase + (long)kt * 512 + half * 32;
        #pragma unroll
        for (int x = 0; x < 4; x++) bb[x] = __ldg(p + 64 * x);
    };

    // ldmatrix lane address (fixed per thread); warp rows wm*32 .. +31
    const uint32_t arow = (uint32_t)((wm * 32 + (lane & 7) + ((lane >> 3) & 1) * 8) * ASTRIDE_B
                                     + (lane >> 4) * 16);

    auto mma_half = [&](int kt, int half, const uint4* bb) {
        uint32_t a0r = smem_u32 + (kt % NSTG) * ABUF + arow;
        uint32_t a1r = a0r + 16 * ASTRIDE_B;
        #pragma unroll
        for (int k2 = 0; k2 < 2; k2++) {
            int ks = half * 2 + k2;
            uint32_t a0[4], a1[4];
            ldsm4(a0, a0r + ks * 32);
            ldsm4(a1, a1r + ks * 32);
            #pragma unroll
            for (int ni = 0; ni < 4; ni++) {
                uint4 w = bb[ni];
                uint32_t b0 = k2 ? w.z : w.x;
                uint32_t b1 = k2 ? w.w : w.y;
                mma_f16(acc[0][ni], a0, b0, b1);
                mma_f16(acc[1][ni], a1, b0, b1);
            }
        }
    };

    // Prologue: 4 A stages pending; group's first lo-half B
    issueA(0); issueA(1); issueA(2); issueA(3);
    uint4 bbL0[4], bbL1[4], bbH[4];
    loadBh(g, 0, bbL0);

    // Pair-of-pairs loop (nt % 4 == 0): keeps all B buffers in static registers.
    for (int ktp = 0; ktp < nt; ktp += 4) {
        // ---- pair A: my tile = ktp + g, lo buffer bbL0 ----
        int my = ktp + g;
        loadBh(my, 1, bbH);              // covered by wait+sync+lo-mma
        CP_WAIT2();
        __syncthreads();                 // stages ktp, ktp+1 ready
        issue2(ktp + 4, ktp + 5);
        mma_half(my, 0, bbL0);
        loadBh(my + 2, 0, bbL1);         // next pair's lo (~1 pair ahead)
        mma_half(my, 1, bbH);
        // ---- pair B: my tile = ktp + 2 + g, lo buffer bbL1 ----
        int my2 = ktp + 2 + g;
        loadBh(my2, 1, bbH);
        CP_WAIT2();
        __syncthreads();                 // stages ktp+2, ktp+3 ready
        issue2(ktp + 6, ktp + 7);
        mma_half(my2, 0, bbL1);
        if (my2 + 2 < nt) loadBh(my2 + 2, 0, bbL0);
        mma_half(my2, 1, bbH);
    }
    CP_WAIT0();
    __syncthreads();   // before reusing stage ring as partial-gate buffers

    // Epilogue 1: each group writes its partial gates to its own smem region [64][68]
    {
        float* part = (float*)smem + g * (64 * 68);
        #pragma unroll
        for (int mi = 0; mi < 2; mi++)
            #pragma unroll
            for (int ni = 0; ni < 4; ni++) {
                int row = wm * 32 + mi * 16 + r4;
                int col = wn * 32 + ni * 8 + kc * 2;
                float* p = part + row * 68 + col;
                p[0]          = acc[mi][ni][0];
                p[1]          = acc[mi][ni][1];
                p[8 * 68]     = acc[mi][ni][2];
                p[8 * 68 + 1] = acc[mi][ni][3];
            }
    }
    __syncthreads();

    // Epilogue 2: sum group partials, cell update, store h (1024 h / CTA, 4 per thread)
    #pragma unroll
    for (int j = 0; j < 4; j++) {
        int idx = j * NTH + tid;
        int row = idx >> 4, u = idx & 15;
        const float* p0 = (const float*)smem + row * 68;
        const float* p1 = p0 + 64 * 68;
        float gi = p0[u]      + p1[u]      + biasL[u];
        float gf = p0[16 + u] + p1[16 + u] + biasL[16 + u];
        float gg = p0[32 + u] + p1[32 + u] + biasL[32 + u];
        float go = p0[48 + u] + p1[48 + u] + biasL[48 + u];
        float ii = fsig(gi), ff = fsig(gf);
        float g2 = ftanh(gg), oo = fsig(go);
        float cn = ff * cst[j] + ii * g2;
        cst[j] = cn;
        float h = oo * ftanh(cn);
        if (extra_tanh) h = ftanh(h);
        __half hh = __float2half_rn(h);
        __stcg((unsigned short*)&hout[(long)(mb * MT + row) * H_ + hb * HB + u],
               __half_as_ushort(hh));
    }
}

__global__ void __launch_bounds__(NTH, 2) lstm_fused(
    const float* __restrict__ bih1, const float* __restrict__ bhh1,
    const float* __restrict__ bih2, const float* __restrict__ bhh2,
    const float* __restrict__ Wout, const float* __restrict__ bout,
    float* __restrict__ out)
{
    extern __shared__ char smem[];
    uint32_t smem_u32;
    asm("{ .reg .u64 t; cvta.to.shared.u64 t, %1; cvt.u32.u64 %0, t; }"
        : "=r"(smem_u32) : "l"(smem));
    const int tid = threadIdx.x;
    const int mb = (int)(blockIdx.x >> 6);   // 0..3
    const int hb = (int)(blockIdx.x & 63);   // 0..63
    float* bias_s = (float*)(smem + BIAS_OFF);

    for (int i = tid; i < MT * HB; i += NTH) {
        int r = i >> 4, c = i & 15;
        g_h1[0][mb * MT + r][hb * HB + c] = __float2half(0.f);
        g_h2[0][mb * MT + r][hb * HB + c] = __float2half(0.f);
    }
    if (tid < 128) {
        int l = tid >> 6, g = (tid >> 4) & 3, u = tid & 15;
        int grow = g * H_ + hb * HB + u;
        bias_s[tid] = (l == 0) ? (bih1[grow] + bhh1[grow]) : (bih2[grow] + bhh2[grow]);
    }
    float c1[4], c2[4];
    #pragma unroll
    for (int j = 0; j < 4; j++) { c1[j] = 0.f; c2[j] = 0.f; }
    __syncthreads();
    grid_barrier();

    const uint4* wp1 = g_Wp1h + (long)hb * NT1 * 512;
    const uint4* wp2 = g_Wp2h + (long)hb * NT2 * 512;

    for (int t = 0; t < T_; t++) {
        int rb = t & 1, wb = rb ^ 1;
        {
            LayerCtx L;
            L.a0 = g_yh + (long)(mb * MT) * (T_ * F_) + (long)t * F_;
            L.a0s = (long)(T_ * F_);
            L.ks0 = F_ / KT;                 // 4
            L.a1 = &g_h1[rb][mb * MT][0];
            L.wp = wp1;
            L.nt = NT1;
            run_layer(smem, smem_u32, L, bias_s, c1, &g_h1[wb][0][0], mb, hb, false);
        }
        grid_barrier();
        {
            LayerCtx L;
            L.a0 = &g_h1[wb][mb * MT][0];
            L.a0s = (long)H_;
            L.ks0 = H_ / KT;                 // 16
            L.a1 = &g_h2[rb][mb * MT][0];
            L.wp = wp2;
            L.nt = NT2;
            run_layer(smem, smem_u32, L, bias_s + 64, c2, &g_h2[wb][0][0], mb, hb, true);
        }
        // single barrier per step: remaining hazards ordered by step t+1's barrier (R5)
    }
    grid_barrier();

    // Output projection: h2 final in buffer 0 (T even). First 128 CTAs, 1 elem/thread.
    {
        int gid = (int)blockIdx.x * NTH + tid;
        if (gid < B_ * C_) {
            int b = gid >> 7, cc = gid & 127;
            float acc = __ldg(&bout[cc]);
            const __half* hr = &g_h2[0][b][0];
            const float*  wr = &Wout[(long)cc * H_];
            #pragma unroll 4
            for (int k = 0; k < H_ / 8; k++) {
                uint4 hk = __ldcg((const uint4*)(hr + k * 8));
                const __half2* hp = (const __half2*)&hk;
                float4 w0 = __ldg((const float4*)(wr + k * 8));
                float4 w1 = __ldg((const float4*)(wr + k * 8 + 4));
                float2 p0 = __half22float2(hp[0]);
                float2 p1 = __half22float2(hp[1]);
                float2 p2 = __half22float2(hp[2]);
                float2 p3 = __half22float2(hp[3]);
                acc += p0.x * w0.x + p0.y * w0.y + p1.x * w0.z + p1.y * w0.w;
                acc += p2.x * w1.x + p2.y * w1.y + p3.x * w1.z + p3.y * w1.w;
            }
            out[gid] = fmaxf(acc, 0.f);
        }
    }
}

extern "C" void kernel_launch(void* const* d_in, const int* in_sizes, int n_in,
                              void* d_out, int out_size) {
    const float* y    = (const float*)d_in[0];
    const float* Wih1 = (const float*)d_in[1];
    const float* Whh1 = (const float*)d_in[2];
    const float* bih1 = (const float*)d_in[3];
    const float* bhh1 = (const float*)d_in[4];
    const float* Wih2 = (const float*)d_in[5];
    const float* Whh2 = (const float*)d_in[6];
    const float* bih2 = (const float*)d_in[7];
    const float* bhh2 = (const float*)d_in[8];
    const float* Wout = (const float*)d_in[9];
    const float* bout = (const float*)d_in[10];
    float* out = (float*)d_out;

    static int smem_set = 0;
    if (!smem_set) {
        cudaFuncSetAttribute(lstm_fused, cudaFuncAttributeMaxDynamicSharedMemorySize, SMEM_BYTES);
        smem_set = 1;
    }

    prep_kernel<<<2048, 256>>>(y, Wih1, Whh1, Wih2, Whh2);
    lstm_fused<<<NCTA, NTH, SMEM_BYTES>>>(bih1, bhh1, bih2, bhh2, Wout, bout, out);
}